// round 12
// baseline (speedup 1.0000x reference)
#include <cuda_runtime.h>
#include <cuda_fp16.h>

#define Bb   4
#define Nn   2048
#define BN   (Bb*Nn)      // 8192
#define DIM  64
#define FIN  32
#define MAXD 384
#define SCALE 0.25f

// ---------------- device scratch (static, allocation-free) ----------------
// Double-buffered q/k/v: layer i reads buffer i&1, fused next-layer QKV writes (i+1)&1.
__device__ __align__(256) float  g_q[2][BN*DIM];
__device__ __align__(256) __half g_kh[2][BN*DIM];
__device__ __align__(256) __half g_vh[2][BN*DIM];
__device__ unsigned short g_nbr[(size_t)BN*MAXD];
__device__ int g_cnt[BN];

// ---------------- LN + QKV body: 8 rows; writes q/k/v buffer wbuf ----------------
__device__ __forceinline__ void ln_qkv_body8(float (*hs)[DIM], float* mu_s, float* rs_s,
                                             int tid, int row0, int nthr, int wbuf,
                                             const float* __restrict__ lng,
                                             const float* __restrict__ lnb,
                                             const float* __restrict__ Wq,
                                             const float* __restrict__ bq,
                                             const float* __restrict__ Wkv,
                                             const float* __restrict__ bkv) {
    if (tid < 64) {
        int g = tid >> 3, cc = tid & 7;
        float4 xa = *(const float4*)&hs[g][cc * 8];
        float4 xb = *(const float4*)&hs[g][cc * 8 + 4];
        float s1 = xa.x + xa.y + xa.z + xa.w + xb.x + xb.y + xb.z + xb.w;
        float s2 = xa.x * xa.x + xa.y * xa.y + xa.z * xa.z + xa.w * xa.w
                 + xb.x * xb.x + xb.y * xb.y + xb.z * xb.z + xb.w * xb.w;
        #pragma unroll
        for (int ofs = 1; ofs <= 4; ofs <<= 1) {
            s1 += __shfl_xor_sync(0xffffffffu, s1, ofs);
            s2 += __shfl_xor_sync(0xffffffffu, s2, ofs);
        }
        if (cc == 0) {
            float m = s1 * (1.f / DIM);
            mu_s[g] = m;
            rs_s[g] = rsqrtf(s2 * (1.f / DIM) - m * m + 1e-5f);
        }
    }
    __syncthreads();
    for (int i = tid; i < 8 * DIM; i += nthr) {
        int r = i >> 6, cix = i & 63;
        hs[r][cix] = (hs[r][cix] - mu_s[r]) * rs_s[r] * __ldg(lng + cix) + __ldg(lnb + cix);
    }
    __syncthreads();

    if (tid >= 192) return;
    int o = tid;
    const float* wp; int ws; float bias;
    if (o < 64)       { wp = Wq + o;         ws = 64;  bias = __ldg(bq + o); }
    else              { wp = Wkv + (o - 64); ws = 128; bias = __ldg(bkv + (o - 64)); }

    float acc[8];
    #pragma unroll
    for (int r = 0; r < 8; r++) acc[r] = bias;

    #pragma unroll 4
    for (int in4 = 0; in4 < 16; in4++) {
        float w0 = __ldg(wp + (4 * in4 + 0) * ws);
        float w1 = __ldg(wp + (4 * in4 + 1) * ws);
        float w2 = __ldg(wp + (4 * in4 + 2) * ws);
        float w3 = __ldg(wp + (4 * in4 + 3) * ws);
        #pragma unroll
        for (int r = 0; r < 8; r++) {
            float4 h4 = *(const float4*)&hs[r][4 * in4];
            acc[r] += h4.x * w0 + h4.y * w1 + h4.z * w2 + h4.w * w3;
        }
    }
    if (o < 64) {
        #pragma unroll
        for (int r = 0; r < 8; r++) g_q[wbuf][(size_t)(row0 + r) * DIM + o] = acc[r];
    } else if (o < 128) {
        #pragma unroll
        for (int r = 0; r < 8; r++) g_kh[wbuf][(size_t)(row0 + r) * DIM + (o - 64)] = __float2half(acc[r]);
    } else {
        #pragma unroll
        for (int r = 0; r < 8; r++) g_vh[wbuf][(size_t)(row0 + r) * DIM + (o - 128)] = __float2half(acc[r]);
    }
}

// ---------------- 1) merged front: build_nbr (blocks 0..1023) + fc_ln_qkv (1024..2047) ----------------
__global__ __launch_bounds__(256) void front_kernel(const float* __restrict__ adj,
                                                    const float* __restrict__ nf,
                                                    const float* __restrict__ Wfc,
                                                    const float* __restrict__ bfc,
                                                    float* __restrict__ x,
                                                    const float* __restrict__ lng,
                                                    const float* __restrict__ lnb,
                                                    const float* __restrict__ Wq,
                                                    const float* __restrict__ bq,
                                                    const float* __restrict__ Wkv,
                                                    const float* __restrict__ bkv) {
    int tid = threadIdx.x;
    if (blockIdx.x < BN / 8) {
        // ---- neighbor-list build: warp per row ----
        int warp = blockIdx.x * 8 + (tid >> 5);
        int lane = tid & 31;
        const float4* a4 = (const float4*)(adj + (size_t)warp * Nn);
        unsigned short* nb = g_nbr + (size_t)warp * MAXD;
        unsigned lmask = (1u << lane) - 1u;
        int cnt = 0;
        for (int j0 = 0; j0 < Nn; j0 += 128) {
            float4 v = a4[(j0 >> 2) + lane];
            int jbase = j0 + 4 * lane;
            #pragma unroll
            for (int comp = 0; comp < 4; comp++) {
                float val = (comp == 0) ? v.x : (comp == 1) ? v.y : (comp == 2) ? v.z : v.w;
                unsigned m = __ballot_sync(0xffffffffu, val > 0.f);
                if (val > 0.f) {
                    int pos = cnt + __popc(m & lmask);
                    if (pos < MAXD) nb[pos] = (unsigned short)(jbase + comp);
                }
                cnt += __popc(m);
            }
        }
        if (lane == 0) g_cnt[warp] = min(cnt, MAXD);
        return;
    }

    // ---- fc + ReLU + LN + QKV (layer 0), writes q/k/v buffer 0 ----
    __shared__ float hs[8][DIM];
    __shared__ float nfs[8][FIN];
    __shared__ float mu_s[8], rs_s[8];
    int row0 = (blockIdx.x - BN / 8) * 8;

    const float4* nv = (const float4*)(nf + (size_t)row0 * FIN);
    float4* nsv = (float4*)&nfs[0][0];
    for (int i = tid; i < 64; i += 256) nsv[i] = nv[i];
    __syncthreads();

    for (int i = tid; i < 8 * DIM; i += 256) {
        int r = i >> 6, cix = i & 63;
        float acc = __ldg(bfc + cix);
        #pragma unroll
        for (int k2 = 0; k2 < FIN; k2++) acc += nfs[r][k2] * __ldg(Wfc + k2 * DIM + cix);
        acc = fmaxf(acc, 0.f);
        hs[r][cix] = acc;
        x[(size_t)(row0 + r) * DIM + cix] = acc;
    }
    __syncthreads();

    ln_qkv_body8(hs, mu_s, rs_s, tid, row0, 256, 0, lng, lnb, Wq, bq, Wkv, bkv);
}

// ---------------- attn phase: 8 warps, warp per row, reads buffer rbuf ----------------
__device__ __forceinline__ void attn_phase(float (*os)[68], int row0, int rbuf) {
    int lane = threadIdx.x & 31;
    int warp = threadIdx.x >> 5;
    int row = row0 + warp;
    int part = lane >> 3;          // 0..3 neighbor split
    int c = lane & 7;              // 0..7 column chunk (8 halves each)
    bool codd = (lane & 1);
    int b_base = row & ~(Nn - 1);

    const float* qbuf = g_q[rbuf];
    const __half* kbuf = g_kh[rbuf];
    const __half* vbuf = g_vh[rbuf];

    const float4* qp = (const float4*)(qbuf + (size_t)row * DIM);
    float4 q0 = qp[2 * c];
    float4 q1 = qp[2 * c + 1];

    float a0 = 0.f, a1 = 0.f, a2 = 0.f, a3 = 0.f;
    float a4 = 0.f, a5 = 0.f, a6 = 0.f, a7 = 0.f;
    float l = 0.f;

    int deg = g_cnt[row];
    int dmax = (deg + 7) & ~7;
    const unsigned short* nb = g_nbr + (size_t)row * MAXD;

    for (int d = part; d < dmax; d += 8) {
        bool actA = d < deg;
        bool actB = d + 4 < deg;
        int jA = actA ? nb[d] : nb[0];
        int jB = actB ? nb[d + 4] : nb[0];
        const uint4* kpA = (const uint4*)(kbuf + (size_t)(b_base + jA) * DIM);
        const uint4* kpB = (const uint4*)(kbuf + (size_t)(b_base + jB) * DIM);
        const uint4* vpA = (const uint4*)(vbuf + (size_t)(b_base + jA) * DIM);
        const uint4* vpB = (const uint4*)(vbuf + (size_t)(b_base + jB) * DIM);
        uint4 kA = kpA[c];
        uint4 kB = kpB[c];
        uint4 vA = vpA[c];
        uint4 vB = vpB[c];

        float2 ka0 = __half22float2(*reinterpret_cast<const __half2*>(&kA.x));
        float2 ka1 = __half22float2(*reinterpret_cast<const __half2*>(&kA.y));
        float2 ka2 = __half22float2(*reinterpret_cast<const __half2*>(&kA.z));
        float2 ka3 = __half22float2(*reinterpret_cast<const __half2*>(&kA.w));
        float2 kb0 = __half22float2(*reinterpret_cast<const __half2*>(&kB.x));
        float2 kb1 = __half22float2(*reinterpret_cast<const __half2*>(&kB.y));
        float2 kb2 = __half22float2(*reinterpret_cast<const __half2*>(&kB.z));
        float2 kb3 = __half22float2(*reinterpret_cast<const __half2*>(&kB.w));

        float sA = q0.x * ka0.x + q0.y * ka0.y + q0.z * ka1.x + q0.w * ka1.y
                 + q1.x * ka2.x + q1.y * ka2.y + q1.z * ka3.x + q1.w * ka3.y;
        float sB = q0.x * kb0.x + q0.y * kb0.y + q0.z * kb1.x + q0.w * kb1.y
                 + q1.x * kb2.x + q1.y * kb2.y + q1.z * kb3.x + q1.w * kb3.y;

        // lane-pair specialization: even lane -> full sA, odd lane -> full sB
        // (even keeps its sA partial, receives partner's sA partial; symmetric odd)
        float sendv = codd ? sA : sB;
        float keepv = codd ? sB : sA;
        float recv = __shfl_xor_sync(0xffffffffu, sendv, 1);
        float sfull = keepv + recv;

        bool pact = codd ? actB : actA;
        float p = pact ? __expf(sfull * SCALE) : 0.f;
        float pother = __shfl_xor_sync(0xffffffffu, p, 1);
        float pA = codd ? pother : p;
        float pB = codd ? p : pother;
        l += pA + pB;

        float2 va0 = __half22float2(*reinterpret_cast<const __half2*>(&vA.x));
        float2 va1 = __half22float2(*reinterpret_cast<const __half2*>(&vA.y));
        float2 va2 = __half22float2(*reinterpret_cast<const __half2*>(&vA.z));
        float2 va3 = __half22float2(*reinterpret_cast<const __half2*>(&vA.w));
        float2 vb0 = __half22float2(*reinterpret_cast<const __half2*>(&vB.x));
        float2 vb1 = __half22float2(*reinterpret_cast<const __half2*>(&vB.y));
        float2 vb2 = __half22float2(*reinterpret_cast<const __half2*>(&vB.z));
        float2 vb3 = __half22float2(*reinterpret_cast<const __half2*>(&vB.w));

        a0 += pA * va0.x + pB * vb0.x;
        a1 += pA * va0.y + pB * vb0.y;
        a2 += pA * va1.x + pB * vb1.x;
        a3 += pA * va1.y + pB * vb1.y;
        a4 += pA * va2.x + pB * vb2.x;
        a5 += pA * va2.y + pB * vb2.y;
        a6 += pA * va3.x + pB * vb3.x;
        a7 += pA * va3.y + pB * vb3.y;
    }

    #pragma unroll
    for (int ofs = 8; ofs <= 16; ofs <<= 1) {
        l  += __shfl_xor_sync(0xffffffffu, l,  ofs);
        a0 += __shfl_xor_sync(0xffffffffu, a0, ofs);
        a1 += __shfl_xor_sync(0xffffffffu, a1, ofs);
        a2 += __shfl_xor_sync(0xffffffffu, a2, ofs);
        a3 += __shfl_xor_sync(0xffffffffu, a3, ofs);
        a4 += __shfl_xor_sync(0xffffffffu, a4, ofs);
        a5 += __shfl_xor_sync(0xffffffffu, a5, ofs);
        a6 += __shfl_xor_sync(0xffffffffu, a6, ofs);
        a7 += __shfl_xor_sync(0xffffffffu, a7, ofs);
    }

    if (part == 0) {
        float inv = 1.f / l;
        float4* op = (float4*)&os[warp][8 * c];
        op[0] = make_float4(a0 * inv, a1 * inv, a2 * inv, a3 * inv);
        op[1] = make_float4(a4 * inv, a5 * inv, a6 * inv, a7 * inv);
    }
}

// ---------------- outgate phase: ALL 256 threads, 32 threads/row (2 cols each) ----------------
__device__ __forceinline__ void outgate_body8(float (*os)[68], float* __restrict__ x,
                                              int tid, int row0,
                                              const float* __restrict__ Wo,
                                              const float* __restrict__ bo,
                                              const float* __restrict__ Wg,
                                              float (*hs)[DIM]) {
    int r = tid >> 5, c = tid & 31;
    int row = row0 + r;
    int col0 = c * 2;

    // 4 split accumulators (2 cols x even/odd input) to halve the FMA chain
    float p0a = __ldg(bo + col0), p1a = __ldg(bo + col0 + 1);
    float p0b = 0.f, p1b = 0.f;

    float2 xa = *(const float2*)(x + (size_t)row * DIM + col0);
    float xr0 = xa.x, xr1 = xa.y;

    #pragma unroll 8
    for (int in = 0; in < DIM; in += 2) {
        float ov0 = os[r][in];
        float ov1 = os[r][in + 1];
        float2 w0 = *(const float2*)(Wo + in * DIM + col0);
        float2 w1 = *(const float2*)(Wo + (in + 1) * DIM + col0);
        p0a += ov0 * w0.x; p1a += ov0 * w0.y;
        p0b += ov1 * w1.x; p1b += ov1 * w1.y;
    }
    float po0 = p0a + p0b;
    float po1 = p1a + p1b;

    float gp = po0 * __ldg(Wg + col0) + xr0 * __ldg(Wg + 64 + col0)
             + (po0 - xr0) * __ldg(Wg + 128 + col0)
             + po1 * __ldg(Wg + col0 + 1) + xr1 * __ldg(Wg + 64 + col0 + 1)
             + (po1 - xr1) * __ldg(Wg + 128 + col0 + 1);
    #pragma unroll
    for (int ofs = 1; ofs <= 16; ofs <<= 1)
        gp += __shfl_xor_sync(0xffffffffu, gp, ofs);

    float gt = 1.f / (1.f + __expf(-gp));
    float o0 = po0 * gt + xr0 * (1.f - gt);
    float o1 = po1 * gt + xr1 * (1.f - gt);

    *(float2*)(x + (size_t)row * DIM + col0) = make_float2(o0, o1);
    if (hs) {
        hs[r][col0] = o0;
        hs[r][col0 + 1] = o1;
    }
}

// ---------------- 2) fused layer: attn(read rbuf) + outgate + LN/QKV(write rbuf^1) ----------------
__global__ __launch_bounds__(256) void layer_kernel(float* __restrict__ x, int rbuf,
                                                    const float* __restrict__ Wo,
                                                    const float* __restrict__ bo,
                                                    const float* __restrict__ Wg,
                                                    const float* __restrict__ lng,
                                                    const float* __restrict__ lnb,
                                                    const float* __restrict__ Wq,
                                                    const float* __restrict__ bq,
                                                    const float* __restrict__ Wkv,
                                                    const float* __restrict__ bkv) {
    __shared__ float os[8][68];
    __shared__ float hs[8][DIM];
    __shared__ float mu_s[8], rs_s[8];
    int tid = threadIdx.x;         // 256
    int row0 = blockIdx.x * 8;

    attn_phase(os, row0, rbuf);
    __syncthreads();

    outgate_body8(os, x, tid, row0, Wo, bo, Wg, hs);
    __syncthreads();

    ln_qkv_body8(hs, mu_s, rs_s, tid, row0, 256, rbuf ^ 1, lng, lnb, Wq, bq, Wkv, bkv);
}

// ---------------- 3) final layer: attn + outgate only ----------------
__global__ __launch_bounds__(256) void layer_final_kernel(float* __restrict__ x, int rbuf,
                                                          const float* __restrict__ Wo,
                                                          const float* __restrict__ bo,
                                                          const float* __restrict__ Wg) {
    __shared__ float os[8][68];
    int tid = threadIdx.x;         // 256
    int row0 = blockIdx.x * 8;

    attn_phase(os, row0, rbuf);
    __syncthreads();

    outgate_body8(os, x, tid, row0, Wo, bo, Wg, 0);
}

// ---------------- launch ----------------
extern "C" void kernel_launch(void* const* d_in, const int* in_sizes, int n_in,
                              void* d_out, int out_size) {
    const float* nf   = (const float*)d_in[0];
    const float* adj  = (const float*)d_in[1];
    const float* Wfc  = (const float*)d_in[2];
    const float* bfc  = (const float*)d_in[3];
    const float* lng  = (const float*)d_in[4];
    const float* lnb  = (const float*)d_in[5];
    const float* Wq   = (const float*)d_in[6];
    const float* bq   = (const float*)d_in[7];
    const float* Wkv  = (const float*)d_in[8];
    const float* bkv  = (const float*)d_in[9];
    const float* Wo   = (const float*)d_in[10];
    const float* bo   = (const float*)d_in[11];
    const float* Wg   = (const float*)d_in[12];
    float* x = (float*)d_out;

    front_kernel<<<2 * (BN / 8), 256>>>(adj, nf, Wfc, bfc, x,
                                        lng, lnb, Wq, bq, Wkv, bkv);
    for (int i = 0; i < 2; i++) {
        layer_kernel<<<BN / 8, 256>>>(x, i & 1,
                                      Wo + i * 64 * 64, bo + i * 64, Wg + i * 192,
                                      lng + (i + 1) * 64, lnb + (i + 1) * 64,
                                      Wq + (i + 1) * 64 * 64, bq + (i + 1) * 64,
                                      Wkv + (i + 1) * 64 * 128, bkv + (i + 1) * 128);
    }
    layer_final_kernel<<<BN / 8, 256>>>(x, 0, Wo + 2 * 64 * 64, bo + 2 * 64, Wg + 2 * 192);
}

// round 16
// speedup vs baseline: 1.1179x; 1.1179x over previous
#include <cuda_runtime.h>
#include <cuda_fp16.h>

#define Bb   4
#define Nn   2048
#define BN   (Bb*Nn)      // 8192
#define DIM  64
#define FIN  32
#define MAXD 384
#define SCALE 0.25f

// ---------------- device scratch (static, allocation-free) ----------------
// Double-buffered q/k/v: layer i reads buffer i&1, fused next-layer QKV writes (i+1)&1.
__device__ __align__(256) float  g_q[2][BN*DIM];
__device__ __align__(256) __half g_kh[2][BN*DIM];
__device__ __align__(256) __half g_vh[2][BN*DIM];
__device__ unsigned short g_nbr[(size_t)BN*MAXD];
__device__ int g_cnt[BN];

// ---------------- LN + QKV body: 8 rows; writes q/k/v buffer wbuf ----------------
__device__ __forceinline__ void ln_qkv_body8(float (*hs)[DIM], float* mu_s, float* rs_s,
                                             int tid, int row0, int nthr, int wbuf,
                                             const float* __restrict__ lng,
                                             const float* __restrict__ lnb,
                                             const float* __restrict__ Wq,
                                             const float* __restrict__ bq,
                                             const float* __restrict__ Wkv,
                                             const float* __restrict__ bkv) {
    if (tid < 64) {
        int g = tid >> 3, cc = tid & 7;
        float4 xa = *(const float4*)&hs[g][cc * 8];
        float4 xb = *(const float4*)&hs[g][cc * 8 + 4];
        float s1 = xa.x + xa.y + xa.z + xa.w + xb.x + xb.y + xb.z + xb.w;
        float s2 = xa.x * xa.x + xa.y * xa.y + xa.z * xa.z + xa.w * xa.w
                 + xb.x * xb.x + xb.y * xb.y + xb.z * xb.z + xb.w * xb.w;
        #pragma unroll
        for (int ofs = 1; ofs <= 4; ofs <<= 1) {
            s1 += __shfl_xor_sync(0xffffffffu, s1, ofs);
            s2 += __shfl_xor_sync(0xffffffffu, s2, ofs);
        }
        if (cc == 0) {
            float m = s1 * (1.f / DIM);
            mu_s[g] = m;
            rs_s[g] = rsqrtf(s2 * (1.f / DIM) - m * m + 1e-5f);
        }
    }
    __syncthreads();
    for (int i = tid; i < 8 * DIM; i += nthr) {
        int r = i >> 6, cix = i & 63;
        hs[r][cix] = (hs[r][cix] - mu_s[r]) * rs_s[r] * __ldg(lng + cix) + __ldg(lnb + cix);
    }
    __syncthreads();

    if (tid >= 192) return;
    int o = tid;
    const float* wp; int ws; float bias;
    if (o < 64)       { wp = Wq + o;         ws = 64;  bias = __ldg(bq + o); }
    else              { wp = Wkv + (o - 64); ws = 128; bias = __ldg(bkv + (o - 64)); }

    float acc[8];
    #pragma unroll
    for (int r = 0; r < 8; r++) acc[r] = bias;

    #pragma unroll 4
    for (int in4 = 0; in4 < 16; in4++) {
        float w0 = __ldg(wp + (4 * in4 + 0) * ws);
        float w1 = __ldg(wp + (4 * in4 + 1) * ws);
        float w2 = __ldg(wp + (4 * in4 + 2) * ws);
        float w3 = __ldg(wp + (4 * in4 + 3) * ws);
        #pragma unroll
        for (int r = 0; r < 8; r++) {
            float4 h4 = *(const float4*)&hs[r][4 * in4];
            acc[r] += h4.x * w0 + h4.y * w1 + h4.z * w2 + h4.w * w3;
        }
    }
    if (o < 64) {
        #pragma unroll
        for (int r = 0; r < 8; r++) g_q[wbuf][(size_t)(row0 + r) * DIM + o] = acc[r];
    } else if (o < 128) {
        #pragma unroll
        for (int r = 0; r < 8; r++) g_kh[wbuf][(size_t)(row0 + r) * DIM + (o - 64)] = __float2half(acc[r]);
    } else {
        #pragma unroll
        for (int r = 0; r < 8; r++) g_vh[wbuf][(size_t)(row0 + r) * DIM + (o - 128)] = __float2half(acc[r]);
    }
}

// ---------------- 1) merged front: build_nbr (blocks 0..1023) + fc_ln_qkv (1024..2047) ----------------
__global__ __launch_bounds__(256) void front_kernel(const float* __restrict__ adj,
                                                    const float* __restrict__ nf,
                                                    const float* __restrict__ Wfc,
                                                    const float* __restrict__ bfc,
                                                    float* __restrict__ x,
                                                    const float* __restrict__ lng,
                                                    const float* __restrict__ lnb,
                                                    const float* __restrict__ Wq,
                                                    const float* __restrict__ bq,
                                                    const float* __restrict__ Wkv,
                                                    const float* __restrict__ bkv) {
    int tid = threadIdx.x;
    if (blockIdx.x < BN / 8) {
        // ---- neighbor-list build: warp per row ----
        int warp = blockIdx.x * 8 + (tid >> 5);
        int lane = tid & 31;
        const float4* a4 = (const float4*)(adj + (size_t)warp * Nn);
        unsigned short* nb = g_nbr + (size_t)warp * MAXD;
        unsigned lmask = (1u << lane) - 1u;
        int cnt = 0;
        for (int j0 = 0; j0 < Nn; j0 += 128) {
            float4 v = a4[(j0 >> 2) + lane];
            int jbase = j0 + 4 * lane;
            #pragma unroll
            for (int comp = 0; comp < 4; comp++) {
                float val = (comp == 0) ? v.x : (comp == 1) ? v.y : (comp == 2) ? v.z : v.w;
                unsigned m = __ballot_sync(0xffffffffu, val > 0.f);
                if (val > 0.f) {
                    int pos = cnt + __popc(m & lmask);
                    if (pos < MAXD) nb[pos] = (unsigned short)(jbase + comp);
                }
                cnt += __popc(m);
            }
        }
        if (lane == 0) g_cnt[warp] = min(cnt, MAXD);
        return;
    }

    // ---- fc + ReLU + LN + QKV (layer 0), writes q/k/v buffer 0 ----
    __shared__ float hs[8][DIM];
    __shared__ float nfs[8][FIN];
    __shared__ float mu_s[8], rs_s[8];
    int row0 = (blockIdx.x - BN / 8) * 8;

    const float4* nv = (const float4*)(nf + (size_t)row0 * FIN);
    float4* nsv = (float4*)&nfs[0][0];
    for (int i = tid; i < 64; i += 256) nsv[i] = nv[i];
    __syncthreads();

    for (int i = tid; i < 8 * DIM; i += 256) {
        int r = i >> 6, cix = i & 63;
        float acc = __ldg(bfc + cix);
        #pragma unroll
        for (int k2 = 0; k2 < FIN; k2++) acc += nfs[r][k2] * __ldg(Wfc + k2 * DIM + cix);
        acc = fmaxf(acc, 0.f);
        hs[r][cix] = acc;
        x[(size_t)(row0 + r) * DIM + cix] = acc;
    }
    __syncthreads();

    ln_qkv_body8(hs, mu_s, rs_s, tid, row0, 256, 0, lng, lnb, Wq, bq, Wkv, bkv);
}

// ---------------- attn phase (round-10 form: 2 independent exps) ----------------
__device__ __forceinline__ void attn_phase(float (*os)[68], int row0, int rbuf) {
    int lane = threadIdx.x & 31;
    int warp = threadIdx.x >> 5;
    int row = row0 + warp;
    int part = lane >> 3;          // 0..3 neighbor split
    int c = lane & 7;              // 0..7 column chunk (8 halves each)
    int b_base = row & ~(Nn - 1);

    const float* qbuf = g_q[rbuf];
    const __half* kbuf = g_kh[rbuf];
    const __half* vbuf = g_vh[rbuf];

    const float4* qp = (const float4*)(qbuf + (size_t)row * DIM);
    float4 q0 = qp[2 * c];
    float4 q1 = qp[2 * c + 1];

    float a0 = 0.f, a1 = 0.f, a2 = 0.f, a3 = 0.f;
    float a4 = 0.f, a5 = 0.f, a6 = 0.f, a7 = 0.f;
    float l = 0.f;

    int deg = g_cnt[row];
    int dmax = (deg + 7) & ~7;
    const unsigned short* nb = g_nbr + (size_t)row * MAXD;

    for (int d = part; d < dmax; d += 8) {
        bool actA = d < deg;
        bool actB = d + 4 < deg;
        int jA = actA ? nb[d] : nb[0];
        int jB = actB ? nb[d + 4] : nb[0];
        const uint4* kpA = (const uint4*)(kbuf + (size_t)(b_base + jA) * DIM);
        const uint4* kpB = (const uint4*)(kbuf + (size_t)(b_base + jB) * DIM);
        const uint4* vpA = (const uint4*)(vbuf + (size_t)(b_base + jA) * DIM);
        const uint4* vpB = (const uint4*)(vbuf + (size_t)(b_base + jB) * DIM);
        uint4 kA = kpA[c];
        uint4 kB = kpB[c];
        uint4 vA = vpA[c];
        uint4 vB = vpB[c];

        float2 ka0 = __half22float2(*reinterpret_cast<const __half2*>(&kA.x));
        float2 ka1 = __half22float2(*reinterpret_cast<const __half2*>(&kA.y));
        float2 ka2 = __half22float2(*reinterpret_cast<const __half2*>(&kA.z));
        float2 ka3 = __half22float2(*reinterpret_cast<const __half2*>(&kA.w));
        float2 kb0 = __half22float2(*reinterpret_cast<const __half2*>(&kB.x));
        float2 kb1 = __half22float2(*reinterpret_cast<const __half2*>(&kB.y));
        float2 kb2 = __half22float2(*reinterpret_cast<const __half2*>(&kB.z));
        float2 kb3 = __half22float2(*reinterpret_cast<const __half2*>(&kB.w));

        float sA = q0.x * ka0.x + q0.y * ka0.y + q0.z * ka1.x + q0.w * ka1.y
                 + q1.x * ka2.x + q1.y * ka2.y + q1.z * ka3.x + q1.w * ka3.y;
        float sB = q0.x * kb0.x + q0.y * kb0.y + q0.z * kb1.x + q0.w * kb1.y
                 + q1.x * kb2.x + q1.y * kb2.y + q1.z * kb3.x + q1.w * kb3.y;

        sA += __shfl_xor_sync(0xffffffffu, sA, 1);
        sB += __shfl_xor_sync(0xffffffffu, sB, 1);

        float pA = actA ? __expf(sA * SCALE) : 0.f;
        float pB = actB ? __expf(sB * SCALE) : 0.f;
        l += pA + pB;

        float2 va0 = __half22float2(*reinterpret_cast<const __half2*>(&vA.x));
        float2 va1 = __half22float2(*reinterpret_cast<const __half2*>(&vA.y));
        float2 va2 = __half22float2(*reinterpret_cast<const __half2*>(&vA.z));
        float2 va3 = __half22float2(*reinterpret_cast<const __half2*>(&vA.w));
        float2 vb0 = __half22float2(*reinterpret_cast<const __half2*>(&vB.x));
        float2 vb1 = __half22float2(*reinterpret_cast<const __half2*>(&vB.y));
        float2 vb2 = __half22float2(*reinterpret_cast<const __half2*>(&vB.z));
        float2 vb3 = __half22float2(*reinterpret_cast<const __half2*>(&vB.w));

        a0 += pA * va0.x + pB * vb0.x;
        a1 += pA * va0.y + pB * vb0.y;
        a2 += pA * va1.x + pB * vb1.x;
        a3 += pA * va1.y + pB * vb1.y;
        a4 += pA * va2.x + pB * vb2.x;
        a5 += pA * va2.y + pB * vb2.y;
        a6 += pA * va3.x + pB * vb3.x;
        a7 += pA * va3.y + pB * vb3.y;
    }

    #pragma unroll
    for (int ofs = 8; ofs <= 16; ofs <<= 1) {
        l  += __shfl_xor_sync(0xffffffffu, l,  ofs);
        a0 += __shfl_xor_sync(0xffffffffu, a0, ofs);
        a1 += __shfl_xor_sync(0xffffffffu, a1, ofs);
        a2 += __shfl_xor_sync(0xffffffffu, a2, ofs);
        a3 += __shfl_xor_sync(0xffffffffu, a3, ofs);
        a4 += __shfl_xor_sync(0xffffffffu, a4, ofs);
        a5 += __shfl_xor_sync(0xffffffffu, a5, ofs);
        a6 += __shfl_xor_sync(0xffffffffu, a6, ofs);
        a7 += __shfl_xor_sync(0xffffffffu, a7, ofs);
    }

    if (part == 0) {
        float inv = 1.f / l;
        float4* op = (float4*)&os[warp][8 * c];
        op[0] = make_float4(a0 * inv, a1 * inv, a2 * inv, a3 * inv);
        op[1] = make_float4(a4 * inv, a5 * inv, a6 * inv, a7 * inv);
    }
}

// ---------------- outgate phase (round-10 form): threads 0..127, 16 threads/row ----------------
__device__ __forceinline__ void outgate_body8(float (*os)[68], float* __restrict__ x,
                                              int tid, int row0,
                                              const float* __restrict__ Wo,
                                              const float* __restrict__ bo,
                                              const float* __restrict__ Wg,
                                              float (*hs)[DIM]) {
    int r = tid >> 4, c = tid & 15;
    int row = row0 + r;
    int col0 = c * 4;

    float po[4];
    #pragma unroll
    for (int t = 0; t < 4; t++) po[t] = __ldg(bo + col0 + t);

    float4 xa = *(const float4*)(x + (size_t)row * DIM + col0);
    float xr[4] = {xa.x, xa.y, xa.z, xa.w};

    for (int in = 0; in < DIM; in++) {
        float ov = os[r][in];
        float4 w0 = *(const float4*)(Wo + in * DIM + col0);
        po[0] += ov * w0.x; po[1] += ov * w0.y; po[2] += ov * w0.z; po[3] += ov * w0.w;
    }

    float gp = 0.f;
    #pragma unroll
    for (int t = 0; t < 4; t++) {
        int col = col0 + t;
        gp += po[t] * __ldg(Wg + col) + xr[t] * __ldg(Wg + 64 + col)
            + (po[t] - xr[t]) * __ldg(Wg + 128 + col);
    }
    #pragma unroll
    for (int ofs = 1; ofs <= 8; ofs <<= 1)
        gp += __shfl_xor_sync(0xffffffffu, gp, ofs);

    float gt = 1.f / (1.f + __expf(-gp));
    #pragma unroll
    for (int t = 0; t < 4; t++) xr[t] = po[t] * gt + xr[t] * (1.f - gt);

    *(float4*)(x + (size_t)row * DIM + col0) = make_float4(xr[0], xr[1], xr[2], xr[3]);
    if (hs) {
        #pragma unroll
        for (int t = 0; t < 4; t++) hs[r][col0 + t] = xr[t];
    }
}

// ---------------- 2) fused layer: attn(read rbuf) + outgate + LN/QKV(write rbuf^1) ----------------
__global__ __launch_bounds__(256) void layer_kernel(float* __restrict__ x, int rbuf,
                                                    const float* __restrict__ Wo,
                                                    const float* __restrict__ bo,
                                                    const float* __restrict__ Wg,
                                                    const float* __restrict__ lng,
                                                    const float* __restrict__ lnb,
                                                    const float* __restrict__ Wq,
                                                    const float* __restrict__ bq,
                                                    const float* __restrict__ Wkv,
                                                    const float* __restrict__ bkv) {
    __shared__ float os[8][68];
    __shared__ float hs[8][DIM];
    __shared__ float mu_s[8], rs_s[8];
    int tid = threadIdx.x;         // 256
    int row0 = blockIdx.x * 8;

    attn_phase(os, row0, rbuf);
    __syncthreads();

    if (tid < 128) outgate_body8(os, x, tid, row0, Wo, bo, Wg, hs);
    __syncthreads();

    ln_qkv_body8(hs, mu_s, rs_s, tid, row0, 256, rbuf ^ 1, lng, lnb, Wq, bq, Wkv, bkv);
}

// ---------------- 3) final layer: attn + outgate only ----------------
__global__ __launch_bounds__(256) void layer_final_kernel(float* __restrict__ x, int rbuf,
                                                          const float* __restrict__ Wo,
                                                          const float* __restrict__ bo,
                                                          const float* __restrict__ Wg) {
    __shared__ float os[8][68];
    int tid = threadIdx.x;         // 256
    int row0 = blockIdx.x * 8;

    attn_phase(os, row0, rbuf);
    __syncthreads();

    if (tid < 128) outgate_body8(os, x, tid, row0, Wo, bo, Wg, 0);
}

// ---------------- launch ----------------
extern "C" void kernel_launch(void* const* d_in, const int* in_sizes, int n_in,
                              void* d_out, int out_size) {
    const float* nf   = (const float*)d_in[0];
    const float* adj  = (const float*)d_in[1];
    const float* Wfc  = (const float*)d_in[2];
    const float* bfc  = (const float*)d_in[3];
    const float* lng  = (const float*)d_in[4];
    const float* lnb  = (const float*)d_in[5];
    const float* Wq   = (const float*)d_in[6];
    const float* bq   = (const float*)d_in[7];
    const float* Wkv  = (const float*)d_in[8];
    const float* bkv  = (const float*)d_in[9];
    const float* Wo   = (const float*)d_in[10];
    const float* bo   = (const float*)d_in[11];
    const float* Wg   = (const float*)d_in[12];
    float* x = (float*)d_out;

    front_kernel<<<2 * (BN / 8), 256>>>(adj, nf, Wfc, bfc, x,
                                        lng, lnb, Wq, bq, Wkv, bkv);
    for (int i = 0; i < 2; i++) {
        layer_kernel<<<BN / 8, 256>>>(x, i & 1,
                                      Wo + i * 64 * 64, bo + i * 64, Wg + i * 192,
                                      lng + (i + 1) * 64, lnb + (i + 1) * 64,
                                      Wq + (i + 1) * 64 * 64, bq + (i + 1) * 64,
                                      Wkv + (i + 1) * 64 * 128, bkv + (i + 1) * 128);
    }
    layer_final_kernel<<<BN / 8, 256>>>(x, 0, Wo + 2 * 64 * 64, bo + 2 * 64, Wg + 2 * 192);
}

// round 17
// speedup vs baseline: 1.1611x; 1.0386x over previous
#include <cuda_runtime.h>
#include <cuda_fp16.h>

#define Bb   4
#define Nn   2048
#define BN   (Bb*Nn)      // 8192
#define DIM  64
#define FIN  32
#define MAXD 384
#define SCALE 0.25f

// ---------------- device scratch (static, allocation-free) ----------------
// Double-buffered q + fused K|V rows: kv row = [K halves 0..63 | V halves 64..127].
__device__ __align__(256) float  g_q[2][BN*DIM];
__device__ __align__(256) __half g_kv[2][(size_t)BN*128];
__device__ unsigned short g_nbr[(size_t)BN*MAXD];
__device__ int g_cnt[BN];

// ---------------- LN + QKV body: 8 rows; writes q/kv buffer wbuf ----------------
__device__ __forceinline__ void ln_qkv_body8(float (*hs)[DIM], float* mu_s, float* rs_s,
                                             int tid, int row0, int nthr, int wbuf,
                                             const float* __restrict__ lng,
                                             const float* __restrict__ lnb,
                                             const float* __restrict__ Wq,
                                             const float* __restrict__ bq,
                                             const float* __restrict__ Wkv,
                                             const float* __restrict__ bkv) {
    if (tid < 64) {
        int g = tid >> 3, cc = tid & 7;
        float4 xa = *(const float4*)&hs[g][cc * 8];
        float4 xb = *(const float4*)&hs[g][cc * 8 + 4];
        float s1 = xa.x + xa.y + xa.z + xa.w + xb.x + xb.y + xb.z + xb.w;
        float s2 = xa.x * xa.x + xa.y * xa.y + xa.z * xa.z + xa.w * xa.w
                 + xb.x * xb.x + xb.y * xb.y + xb.z * xb.z + xb.w * xb.w;
        #pragma unroll
        for (int ofs = 1; ofs <= 4; ofs <<= 1) {
            s1 += __shfl_xor_sync(0xffffffffu, s1, ofs);
            s2 += __shfl_xor_sync(0xffffffffu, s2, ofs);
        }
        if (cc == 0) {
            float m = s1 * (1.f / DIM);
            mu_s[g] = m;
            rs_s[g] = rsqrtf(s2 * (1.f / DIM) - m * m + 1e-5f);
        }
    }
    __syncthreads();
    for (int i = tid; i < 8 * DIM; i += nthr) {
        int r = i >> 6, cix = i & 63;
        hs[r][cix] = (hs[r][cix] - mu_s[r]) * rs_s[r] * __ldg(lng + cix) + __ldg(lnb + cix);
    }
    __syncthreads();

    if (tid >= 192) return;
    int o = tid;
    const float* wp; int ws; float bias;
    if (o < 64)       { wp = Wq + o;         ws = 64;  bias = __ldg(bq + o); }
    else              { wp = Wkv + (o - 64); ws = 128; bias = __ldg(bkv + (o - 64)); }

    float acc[8];
    #pragma unroll
    for (int r = 0; r < 8; r++) acc[r] = bias;

    #pragma unroll 4
    for (int in4 = 0; in4 < 16; in4++) {
        float w0 = __ldg(wp + (4 * in4 + 0) * ws);
        float w1 = __ldg(wp + (4 * in4 + 1) * ws);
        float w2 = __ldg(wp + (4 * in4 + 2) * ws);
        float w3 = __ldg(wp + (4 * in4 + 3) * ws);
        #pragma unroll
        for (int r = 0; r < 8; r++) {
            float4 h4 = *(const float4*)&hs[r][4 * in4];
            acc[r] += h4.x * w0 + h4.y * w1 + h4.z * w2 + h4.w * w3;
        }
    }
    if (o < 64) {
        #pragma unroll
        for (int r = 0; r < 8; r++) g_q[wbuf][(size_t)(row0 + r) * DIM + o] = acc[r];
    } else {
        // K (o in [64,128)) -> kv offset o-64 in [0,64); V (o in [128,192)) -> kv offset o-64 in [64,128)
        #pragma unroll
        for (int r = 0; r < 8; r++)
            g_kv[wbuf][((size_t)(row0 + r) << 7) + (o - 64)] = __float2half(acc[r]);
    }
}

// ---------------- 1) merged front: build_nbr (blocks 0..1023) + fc_ln_qkv (1024..2047) ----------------
__global__ __launch_bounds__(256) void front_kernel(const float* __restrict__ adj,
                                                    const float* __restrict__ nf,
                                                    const float* __restrict__ Wfc,
                                                    const float* __restrict__ bfc,
                                                    float* __restrict__ x,
                                                    const float* __restrict__ lng,
                                                    const float* __restrict__ lnb,
                                                    const float* __restrict__ Wq,
                                                    const float* __restrict__ bq,
                                                    const float* __restrict__ Wkv,
                                                    const float* __restrict__ bkv) {
    int tid = threadIdx.x;
    if (blockIdx.x < BN / 8) {
        // ---- neighbor-list build: warp per row ----
        int warp = blockIdx.x * 8 + (tid >> 5);
        int lane = tid & 31;
        const float4* a4 = (const float4*)(adj + (size_t)warp * Nn);
        unsigned short* nb = g_nbr + (size_t)warp * MAXD;
        unsigned lmask = (1u << lane) - 1u;
        int cnt = 0;
        for (int j0 = 0; j0 < Nn; j0 += 128) {
            float4 v = a4[(j0 >> 2) + lane];
            int jbase = j0 + 4 * lane;
            #pragma unroll
            for (int comp = 0; comp < 4; comp++) {
                float val = (comp == 0) ? v.x : (comp == 1) ? v.y : (comp == 2) ? v.z : v.w;
                unsigned m = __ballot_sync(0xffffffffu, val > 0.f);
                if (val > 0.f) {
                    int pos = cnt + __popc(m & lmask);
                    if (pos < MAXD) nb[pos] = (unsigned short)(jbase + comp);
                }
                cnt += __popc(m);
            }
        }
        if (lane == 0) g_cnt[warp] = min(cnt, MAXD);
        return;
    }

    // ---- fc + ReLU + LN + QKV (layer 0), writes q/kv buffer 0 ----
    __shared__ float hs[8][DIM];
    __shared__ float nfs[8][FIN];
    __shared__ float mu_s[8], rs_s[8];
    int row0 = (blockIdx.x - BN / 8) * 8;

    const float4* nv = (const float4*)(nf + (size_t)row0 * FIN);
    float4* nsv = (float4*)&nfs[0][0];
    for (int i = tid; i < 64; i += 256) nsv[i] = nv[i];
    __syncthreads();

    for (int i = tid; i < 8 * DIM; i += 256) {
        int r = i >> 6, cix = i & 63;
        float acc = __ldg(bfc + cix);
        #pragma unroll
        for (int k2 = 0; k2 < FIN; k2++) acc += nfs[r][k2] * __ldg(Wfc + k2 * DIM + cix);
        acc = fmaxf(acc, 0.f);
        hs[r][cix] = acc;
        x[(size_t)(row0 + r) * DIM + cix] = acc;
    }
    __syncthreads();

    ln_qkv_body8(hs, mu_s, rs_s, tid, row0, 256, 0, lng, lnb, Wq, bq, Wkv, bkv);
}

// ---------------- attn phase: ILP-4, fused K|V rows ----------------
__device__ __forceinline__ void attn_phase(float (*os)[68], int row0, int rbuf) {
    int lane = threadIdx.x & 31;
    int warp = threadIdx.x >> 5;
    int row = row0 + warp;
    int part = lane >> 3;          // 0..3 neighbor split
    int c = lane & 7;              // 0..7 column chunk (8 halves each)
    int b_base = row & ~(Nn - 1);

    const float* qbuf = g_q[rbuf];
    const __half* kvbuf = g_kv[rbuf];

    const float4* qp = (const float4*)(qbuf + (size_t)row * DIM);
    float4 q0 = qp[2 * c];
    float4 q1 = qp[2 * c + 1];

    float a0 = 0.f, a1 = 0.f, a2 = 0.f, a3 = 0.f;
    float a4 = 0.f, a5 = 0.f, a6 = 0.f, a7 = 0.f;
    float l = 0.f;

    int deg = g_cnt[row];
    int dmax = (deg + 15) & ~15;   // uniform trip count, ILP-4 (parts cover residues mod 16)
    const unsigned short* nb = g_nbr + (size_t)row * MAXD;

    for (int d = part; d < dmax; d += 16) {
        bool actA = d      < deg;
        bool actB = d + 4  < deg;
        bool actC = d + 8  < deg;
        bool actD = d + 12 < deg;
        int jA = actA ? nb[d]      : nb[0];
        int jB = actB ? nb[d + 4]  : nb[0];
        int jC = actC ? nb[d + 8]  : nb[0];
        int jD = actD ? nb[d + 12] : nb[0];

        const uint4* pA = (const uint4*)(kvbuf + ((size_t)(b_base + jA) << 7));
        const uint4* pB = (const uint4*)(kvbuf + ((size_t)(b_base + jB) << 7));
        const uint4* pC = (const uint4*)(kvbuf + ((size_t)(b_base + jC) << 7));
        const uint4* pD = (const uint4*)(kvbuf + ((size_t)(b_base + jD) << 7));

        uint4 kA = pA[c];     uint4 kB = pB[c];
        uint4 kC = pC[c];     uint4 kD = pD[c];
        uint4 vA = pA[8 + c]; uint4 vB = pB[8 + c];
        uint4 vC = pC[8 + c]; uint4 vD = pD[8 + c];

        float2 t0, t1, t2, t3;
        // --- dots ---
        t0 = __half22float2(*reinterpret_cast<const __half2*>(&kA.x));
        t1 = __half22float2(*reinterpret_cast<const __half2*>(&kA.y));
        t2 = __half22float2(*reinterpret_cast<const __half2*>(&kA.z));
        t3 = __half22float2(*reinterpret_cast<const __half2*>(&kA.w));
        float sA = q0.x * t0.x + q0.y * t0.y + q0.z * t1.x + q0.w * t1.y
                 + q1.x * t2.x + q1.y * t2.y + q1.z * t3.x + q1.w * t3.y;
        t0 = __half22float2(*reinterpret_cast<const __half2*>(&kB.x));
        t1 = __half22float2(*reinterpret_cast<const __half2*>(&kB.y));
        t2 = __half22float2(*reinterpret_cast<const __half2*>(&kB.z));
        t3 = __half22float2(*reinterpret_cast<const __half2*>(&kB.w));
        float sB = q0.x * t0.x + q0.y * t0.y + q0.z * t1.x + q0.w * t1.y
                 + q1.x * t2.x + q1.y * t2.y + q1.z * t3.x + q1.w * t3.y;
        t0 = __half22float2(*reinterpret_cast<const __half2*>(&kC.x));
        t1 = __half22float2(*reinterpret_cast<const __half2*>(&kC.y));
        t2 = __half22float2(*reinterpret_cast<const __half2*>(&kC.z));
        t3 = __half22float2(*reinterpret_cast<const __half2*>(&kC.w));
        float sC = q0.x * t0.x + q0.y * t0.y + q0.z * t1.x + q0.w * t1.y
                 + q1.x * t2.x + q1.y * t2.y + q1.z * t3.x + q1.w * t3.y;
        t0 = __half22float2(*reinterpret_cast<const __half2*>(&kD.x));
        t1 = __half22float2(*reinterpret_cast<const __half2*>(&kD.y));
        t2 = __half22float2(*reinterpret_cast<const __half2*>(&kD.z));
        t3 = __half22float2(*reinterpret_cast<const __half2*>(&kD.w));
        float sD = q0.x * t0.x + q0.y * t0.y + q0.z * t1.x + q0.w * t1.y
                 + q1.x * t2.x + q1.y * t2.y + q1.z * t3.x + q1.w * t3.y;

        sA += __shfl_xor_sync(0xffffffffu, sA, 1);
        sB += __shfl_xor_sync(0xffffffffu, sB, 1);
        sC += __shfl_xor_sync(0xffffffffu, sC, 1);
        sD += __shfl_xor_sync(0xffffffffu, sD, 1);

        float pAx = actA ? __expf(sA * SCALE) : 0.f;
        float pBx = actB ? __expf(sB * SCALE) : 0.f;
        float pCx = actC ? __expf(sC * SCALE) : 0.f;
        float pDx = actD ? __expf(sD * SCALE) : 0.f;
        l += (pAx + pBx) + (pCx + pDx);

        // --- weighted V accumulation ---
        t0 = __half22float2(*reinterpret_cast<const __half2*>(&vA.x));
        t1 = __half22float2(*reinterpret_cast<const __half2*>(&vA.y));
        t2 = __half22float2(*reinterpret_cast<const __half2*>(&vA.z));
        t3 = __half22float2(*reinterpret_cast<const __half2*>(&vA.w));
        a0 += pAx * t0.x; a1 += pAx * t0.y; a2 += pAx * t1.x; a3 += pAx * t1.y;
        a4 += pAx * t2.x; a5 += pAx * t2.y; a6 += pAx * t3.x; a7 += pAx * t3.y;
        t0 = __half22float2(*reinterpret_cast<const __half2*>(&vB.x));
        t1 = __half22float2(*reinterpret_cast<const __half2*>(&vB.y));
        t2 = __half22float2(*reinterpret_cast<const __half2*>(&vB.z));
        t3 = __half22float2(*reinterpret_cast<const __half2*>(&vB.w));
        a0 += pBx * t0.x; a1 += pBx * t0.y; a2 += pBx * t1.x; a3 += pBx * t1.y;
        a4 += pBx * t2.x; a5 += pBx * t2.y; a6 += pBx * t3.x; a7 += pBx * t3.y;
        t0 = __half22float2(*reinterpret_cast<const __half2*>(&vC.x));
        t1 = __half22float2(*reinterpret_cast<const __half2*>(&vC.y));
        t2 = __half22float2(*reinterpret_cast<const __half2*>(&vC.z));
        t3 = __half22float2(*reinterpret_cast<const __half2*>(&vC.w));
        a0 += pCx * t0.x; a1 += pCx * t0.y; a2 += pCx * t1.x; a3 += pCx * t1.y;
        a4 += pCx * t2.x; a5 += pCx * t2.y; a6 += pCx * t3.x; a7 += pCx * t3.y;
        t0 = __half22float2(*reinterpret_cast<const __half2*>(&vD.x));
        t1 = __half22float2(*reinterpret_cast<const __half2*>(&vD.y));
        t2 = __half22float2(*reinterpret_cast<const __half2*>(&vD.z));
        t3 = __half22float2(*reinterpret_cast<const __half2*>(&vD.w));
        a0 += pDx * t0.x; a1 += pDx * t0.y; a2 += pDx * t1.x; a3 += pDx * t1.y;
        a4 += pDx * t2.x; a5 += pDx * t2.y; a6 += pDx * t3.x; a7 += pDx * t3.y;
    }

    #pragma unroll
    for (int ofs = 8; ofs <= 16; ofs <<= 1) {
        l  += __shfl_xor_sync(0xffffffffu, l,  ofs);
        a0 += __shfl_xor_sync(0xffffffffu, a0, ofs);
        a1 += __shfl_xor_sync(0xffffffffu, a1, ofs);
        a2 += __shfl_xor_sync(0xffffffffu, a2, ofs);
        a3 += __shfl_xor_sync(0xffffffffu, a3, ofs);
        a4 += __shfl_xor_sync(0xffffffffu, a4, ofs);
        a5 += __shfl_xor_sync(0xffffffffu, a5, ofs);
        a6 += __shfl_xor_sync(0xffffffffu, a6, ofs);
        a7 += __shfl_xor_sync(0xffffffffu, a7, ofs);
    }

    if (part == 0) {
        float inv = 1.f / l;
        float4* op = (float4*)&os[warp][8 * c];
        op[0] = make_float4(a0 * inv, a1 * inv, a2 * inv, a3 * inv);
        op[1] = make_float4(a4 * inv, a5 * inv, a6 * inv, a7 * inv);
    }
}

// ---------------- outgate phase: threads 0..127, 16 threads/row ----------------
__device__ __forceinline__ void outgate_body8(float (*os)[68], float* __restrict__ x,
                                              int tid, int row0,
                                              const float* __restrict__ Wo,
                                              const float* __restrict__ bo,
                                              const float* __restrict__ Wg,
                                              float (*hs)[DIM]) {
    int r = tid >> 4, c = tid & 15;
    int row = row0 + r;
    int col0 = c * 4;

    float po[4];
    #pragma unroll
    for (int t = 0; t < 4; t++) po[t] = __ldg(bo + col0 + t);

    float4 xa = *(const float4*)(x + (size_t)row * DIM + col0);
    float xr[4] = {xa.x, xa.y, xa.z, xa.w};

    for (int in = 0; in < DIM; in++) {
        float ov = os[r][in];
        float4 w0 = *(const float4*)(Wo + in * DIM + col0);
        po[0] += ov * w0.x; po[1] += ov * w0.y; po[2] += ov * w0.z; po[3] += ov * w0.w;
    }

    float gp = 0.f;
    #pragma unroll
    for (int t = 0; t < 4; t++) {
        int col = col0 + t;
        gp += po[t] * __ldg(Wg + col) + xr[t] * __ldg(Wg + 64 + col)
            + (po[t] - xr[t]) * __ldg(Wg + 128 + col);
    }
    #pragma unroll
    for (int ofs = 1; ofs <= 8; ofs <<= 1)
        gp += __shfl_xor_sync(0xffffffffu, gp, ofs);

    float gt = 1.f / (1.f + __expf(-gp));
    #pragma unroll
    for (int t = 0; t < 4; t++) xr[t] = po[t] * gt + xr[t] * (1.f - gt);

    *(float4*)(x + (size_t)row * DIM + col0) = make_float4(xr[0], xr[1], xr[2], xr[3]);
    if (hs) {
        #pragma unroll
        for (int t = 0; t < 4; t++) hs[r][col0 + t] = xr[t];
    }
}

// ---------------- 2) fused layer: attn(read rbuf) + outgate + LN/QKV(write rbuf^1) ----------------
__global__ __launch_bounds__(256) void layer_kernel(float* __restrict__ x, int rbuf,
                                                    const float* __restrict__ Wo,
                                                    const float* __restrict__ bo,
                                                    const float* __restrict__ Wg,
                                                    const float* __restrict__ lng,
                                                    const float* __restrict__ lnb,
                                                    const float* __restrict__ Wq,
                                                    const float* __restrict__ bq,
                                                    const float* __restrict__ Wkv,
                                                    const float* __restrict__ bkv) {
    __shared__ float os[8][68];
    __shared__ float hs[8][DIM];
    __shared__ float mu_s[8], rs_s[8];
    int tid = threadIdx.x;         // 256
    int row0 = blockIdx.x * 8;

    attn_phase(os, row0, rbuf);
    __syncthreads();

    if (tid < 128) outgate_body8(os, x, tid, row0, Wo, bo, Wg, hs);
    __syncthreads();

    ln_qkv_body8(hs, mu_s, rs_s, tid, row0, 256, rbuf ^ 1, lng, lnb, Wq, bq, Wkv, bkv);
}

// ---------------- 3) final layer: attn + outgate only ----------------
__global__ __launch_bounds__(256) void layer_final_kernel(float* __restrict__ x, int rbuf,
                                                          const float* __restrict__ Wo,
                                                          const float* __restrict__ bo,
                                                          const float* __restrict__ Wg) {
    __shared__ float os[8][68];
    int tid = threadIdx.x;         // 256
    int row0 = blockIdx.x * 8;

    attn_phase(os, row0, rbuf);
    __syncthreads();

    if (tid < 128) outgate_body8(os, x, tid, row0, Wo, bo, Wg, 0);
}

// ---------------- launch ----------------
extern "C" void kernel_launch(void* const* d_in, const int* in_sizes, int n_in,
                              void* d_out, int out_size) {
    const float* nf   = (const float*)d_in[0];
    const float* adj  = (const float*)d_in[1];
    const float* Wfc  = (const float*)d_in[2];
    const float* bfc  = (const float*)d_in[3];
    const float* lng  = (const float*)d_in[4];
    const float* lnb  = (const float*)d_in[5];
    const float* Wq   = (const float*)d_in[6];
    const float* bq   = (const float*)d_in[7];
    const float* Wkv  = (const float*)d_in[8];
    const float* bkv  = (const float*)d_in[9];
    const float* Wo   = (const float*)d_in[10];
    const float* bo   = (const float*)d_in[11];
    const float* Wg   = (const float*)d_in[12];
    float* x = (float*)d_out;

    front_kernel<<<2 * (BN / 8), 256>>>(adj, nf, Wfc, bfc, x,
                                        lng, lnb, Wq, bq, Wkv, bkv);
    for (int i = 0; i < 2; i++) {
        layer_kernel<<<BN / 8, 256>>>(x, i & 1,
                                      Wo + i * 64 * 64, bo + i * 64, Wg + i * 192,
                                      lng + (i + 1) * 64, lnb + (i + 1) * 64,
                                      Wq + (i + 1) * 64 * 64, bq + (i + 1) * 64,
                                      Wkv + (i + 1) * 64 * 128, bkv + (i + 1) * 128);
    }
    layer_final_kernel<<<BN / 8, 256>>>(x, 0, Wo + 2 * 64 * 64, bo + 2 * 64, Wg + 2 * 192);
}